// round 4
// baseline (speedup 1.0000x reference)
#include <cuda_runtime.h>
#include <cuda_bf16.h>
#include <cstdint>

#define B_   8
#define C_   256
#define H_   96
#define W_   96
#define HW_  (H_*W_)          // 9216
#define G_   4
#define CG_  64
#define HO_  192
#define WO_  192
#define HOWO_ (HO_*WO_)
#define NOUT_ 32

// Scratch coords (ix, iy) per output pixel, layout [n][oy][ox]; 16B-aligned so
// pairs can be read as float4.
__device__ __align__(16) float2 g_coords[B_ * G_ * HO_ * WO_];   // 9.4 MB

// ---------------------------------------------------------------------------
// Kernel 1: offset head. 128 threads, 2 pixels per thread (positions p and
// p+128), weights broadcast from SMEM as float4, double-buffered x loads.
// Grid: 288 blocks (256 px each).
// ---------------------------------------------------------------------------
__global__ __launch_bounds__(128) void dysample_offset_kernel(
    const float* __restrict__ x,
    const float* __restrict__ w_off,
    const float* __restrict__ b_off)
{
    __shared__ __align__(16) float4 w_sh4[NOUT_ * C_ / 4];   // 32 KB, [o][c/4]
    __shared__ float b_sh[NOUT_];

    const int tid = threadIdx.x;
    for (int i = tid; i < NOUT_ * C_ / 4; i += 128)
        w_sh4[i] = ((const float4*)w_off)[i];
    if (tid < NOUT_) b_sh[tid] = b_off[tid];
    __syncthreads();

    const int base = blockIdx.x * 256;        // 9216 % 256 == 0 -> one b per block
    const int b    = base / HW_;
    const int p0   = base % HW_ + tid;
    const int p1   = p0 + 128;

    const float* xp0 = x + (size_t)b * C_ * HW_ + p0;
    const float* xp1 = xp0 + 128;

    float acc0[NOUT_], acc1[NOUT_];
#pragma unroll
    for (int o = 0; o < NOUT_; o++) { acc0[o] = 0.f; acc1[o] = 0.f; }

    float c0[4], c1[4];
#pragma unroll
    for (int j = 0; j < 4; j++) { c0[j] = xp0[j * HW_]; c1[j] = xp1[j * HW_]; }

#pragma unroll 1
    for (int cb = 0; cb < C_; cb += 4) {
        const int cn = (cb + 4 < C_) ? (cb + 4) : (C_ - 4);
        float n0[4], n1[4];
#pragma unroll
        for (int j = 0; j < 4; j++) {
            n0[j] = xp0[(cn + j) * HW_];
            n1[j] = xp1[(cn + j) * HW_];
        }
#pragma unroll
        for (int o = 0; o < NOUT_; o++) {
            const float4 wv = w_sh4[o * (C_ / 4) + (cb >> 2)];
            float t0 = acc0[o], t1 = acc1[o];
            t0 = fmaf(c0[0], wv.x, t0);  t1 = fmaf(c1[0], wv.x, t1);
            t0 = fmaf(c0[1], wv.y, t0);  t1 = fmaf(c1[1], wv.y, t1);
            t0 = fmaf(c0[2], wv.z, t0);  t1 = fmaf(c1[2], wv.z, t1);
            t0 = fmaf(c0[3], wv.w, t0);  t1 = fmaf(c1[3], wv.w, t1);
            acc0[o] = t0; acc1[o] = t1;
        }
#pragma unroll
        for (int j = 0; j < 4; j++) { c0[j] = n0[j]; c1[j] = n1[j]; }
    }

#pragma unroll
    for (int px = 0; px < 2; px++) {
        const int   p   = px ? p1 : p0;
        const float* ac = px ? acc1 : acc0;
        const int h = p / W_;
        const int w = p % W_;
        const float wf = (float)w, hf = (float)h;
#pragma unroll
        for (int gi = 0; gi < G_; gi++) {
#pragma unroll
            for (int sy = 0; sy < 2; sy++) {
#pragma unroll
                for (int sx = 0; sx < 2; sx++) {
                    const int idx = gi * 4 + sy * 2 + sx;
                    float ix = wf + (ac[idx]      + b_sh[idx])      * 0.25f;
                    float iy = hf + (ac[16 + idx] + b_sh[16 + idx]) * 0.25f;
                    ix = fminf(fmaxf(ix, 0.f), (float)(W_ - 1));
                    iy = fminf(fmaxf(iy, 0.f), (float)(H_ - 1));
                    const int n  = b * G_ + gi;
                    const int oy = 2 * h + sy;
                    const int ox = 2 * w + sx;
                    g_coords[((size_t)n * HO_ + oy) * WO_ + ox] = make_float2(ix, iy);
                }
            }
        }
    }
}

// ---------------------------------------------------------------------------
// Kernel 2: bilinear gather, channel-pair-interleaved SMEM tile.
// Block = (n, 4 output rows x 192 cols), 192 threads, 2 ox-pairs per thread.
// Tile: 4 float2 planes (2 channels each) x 4 rows x 96 cols (stride 98).
// All tile loads are LDS.64 (two channels per tap); outputs stored as STG.64.
// ---------------------------------------------------------------------------
#define TR    4
#define TSD2  98     // float2 per row (96 + pad, 16B-aligned rows)

__global__ __launch_bounds__(192) void dysample_sample_kernel(
    const float* __restrict__ x,
    float* __restrict__ out)
{
    __shared__ __align__(16) float2 tile2[4][TR * TSD2];   // 12.5 KB

    const int tid = threadIdx.x;
    const int n   = blockIdx.y;
    const int b   = n >> 2;
    const int gi  = n & 3;
    const int oy0 = blockIdx.x * 4;

    int r0 = (oy0 >> 1) - 1;
    if (r0 < 0) r0 = 0;
    if (r0 > H_ - TR) r0 = H_ - TR;          // 92
    const int r1 = r0 + TR - 1;

    // Per-pair state: k = 0,1 ; each pair = output px (oy0+oyr, 2q) and (.., 2q+1)
    float4 wA[2], wB[2];        // bilinear weights for px0 / px1
    int   off[2][2][4];         // [k][px][tap] tile float2-index (or global idx if fb)
    int   obase[2];             // output float2 index within a channel plane
    int   fb[2];

#pragma unroll
    for (int k = 0; k < 2; k++) {
        const int pr  = tid + k * 192;       // 0..383
        const int oyr = pr / 96;
        const int q   = pr % 96;
        const int ox  = 2 * q;
        const float4 c2 = *(const float4*)&g_coords[((size_t)n * HO_ + oy0 + oyr) * WO_ + ox];

        int okA, okB;
#pragma unroll
        for (int px = 0; px < 2; px++) {
            const float ixf = px ? c2.z : c2.x;
            const float iyf = px ? c2.w : c2.y;
            const float x0f = floorf(ixf), y0f = floorf(iyf);
            const int xi0 = (int)x0f, yi0 = (int)y0f;
            const float wx = ixf - x0f, wy = iyf - y0f;
            const int xi1 = min(xi0 + 1, W_ - 1);
            const int yi1 = min(yi0 + 1, H_ - 1);
            const float4 wv = make_float4((1.f - wy) * (1.f - wx), (1.f - wy) * wx,
                                          wy * (1.f - wx),         wy * wx);
            if (px) wB[k] = wv; else wA[k] = wv;
            const int ok = (yi0 >= r0) && (yi1 <= r1);
            if (px) okB = ok; else okA = ok;
            off[k][px][0] = (yi0 - r0) * TSD2 + xi0;
            off[k][px][1] = (yi0 - r0) * TSD2 + xi1;
            off[k][px][2] = (yi1 - r0) * TSD2 + xi0;
            off[k][px][3] = (yi1 - r0) * TSD2 + xi1;
            // stash global indices in case of fallback (recomputed below if needed)
            if (!ok) {
                off[k][px][0] = yi0 * W_ + xi0;
                off[k][px][1] = yi0 * W_ + xi1;
                off[k][px][2] = yi1 * W_ + xi0;
                off[k][px][3] = yi1 * W_ + xi1;
            }
        }
        fb[k] = !(okA && okB);
        if (fb[k]) {
            // force BOTH pixels of the pair to global indices
#pragma unroll
            for (int px = 0; px < 2; px++) {
                const float ixf = px ? c2.z : c2.x;
                const float iyf = px ? c2.w : c2.y;
                const int xi0 = (int)floorf(ixf);
                const int yi0 = (int)floorf(iyf);
                const int xi1 = min(xi0 + 1, W_ - 1);
                const int yi1 = min(yi0 + 1, H_ - 1);
                off[k][px][0] = yi0 * W_ + xi0;
                off[k][px][1] = yi0 * W_ + xi1;
                off[k][px][2] = yi1 * W_ + xi0;
                off[k][px][3] = yi1 * W_ + xi1;
            }
        }
        obase[k] = (oy0 + oyr) * 96 + q;     // float2 index
    }

    const int ch0 = b * C_ + gi * CG_;
    const float* xg = x + (size_t)ch0 * HW_;
    float* og = out + (size_t)ch0 * HOWO_;

#pragma unroll 1
    for (int cb = 0; cb < CG_; cb += 8) {
        __syncthreads();
        // Load 8 channels as 4 interleaved float2 planes.
        // tasks: plane(4) x row(4) x seg(24 of 4 cols) = 384 -> 2 per thread
#pragma unroll
        for (int t = 0; t < 2; t++) {
            const int task = tid + t * 192;
            const int p    = task / 96;
            const int rem  = task % 96;
            const int r    = rem / 24;
            const int s    = rem % 24;
            const float* b0 = xg + (size_t)(cb + 2 * p) * HW_ + (r0 + r) * W_ + s * 4;
            const float4 e = *(const float4*)b0;
            const float4 o = *(const float4*)(b0 + HW_);
            float2* dst = &tile2[p][r * TSD2 + s * 4];
            *(float4*)&dst[0] = make_float4(e.x, o.x, e.y, o.y);
            *(float4*)&dst[2] = make_float4(e.z, o.z, e.w, o.w);
        }
        __syncthreads();

#pragma unroll
        for (int k = 0; k < 2; k++) {
            const float4 wa = wA[k];
            const float4 wb = wB[k];
            if (!fb[k]) {
#pragma unroll
                for (int p = 0; p < 4; p++) {
                    const float2* tp = tile2[p];
                    const float2 a0 = tp[off[k][0][0]];
                    const float2 a1 = tp[off[k][0][1]];
                    const float2 a2 = tp[off[k][0][2]];
                    const float2 a3 = tp[off[k][0][3]];
                    const float2 b0v = tp[off[k][1][0]];
                    const float2 b1v = tp[off[k][1][1]];
                    const float2 b2v = tp[off[k][1][2]];
                    const float2 b3v = tp[off[k][1][3]];
                    // px0, channels even/odd
                    float e0 = wa.x * a0.x;  e0 = fmaf(wa.y, a1.x, e0);
                    e0 = fmaf(wa.z, a2.x, e0); e0 = fmaf(wa.w, a3.x, e0);
                    float o0 = wa.x * a0.y;  o0 = fmaf(wa.y, a1.y, o0);
                    o0 = fmaf(wa.z, a2.y, o0); o0 = fmaf(wa.w, a3.y, o0);
                    // px1
                    float e1 = wb.x * b0v.x; e1 = fmaf(wb.y, b1v.x, e1);
                    e1 = fmaf(wb.z, b2v.x, e1); e1 = fmaf(wb.w, b3v.x, e1);
                    float o1 = wb.x * b0v.y; o1 = fmaf(wb.y, b1v.y, o1);
                    o1 = fmaf(wb.z, b2v.y, o1); o1 = fmaf(wb.w, b3v.y, o1);

                    float2* oe = (float2*)(og + (size_t)(cb + 2 * p) * HOWO_) + obase[k];
                    float2* oo = (float2*)(og + (size_t)(cb + 2 * p + 1) * HOWO_) + obase[k];
                    *oe = make_float2(e0, e1);
                    *oo = make_float2(o0, o1);
                }
            } else {
#pragma unroll
                for (int p = 0; p < 4; p++) {
#pragma unroll
                    for (int c = 0; c < 2; c++) {
                        const float* g = xg + (size_t)(cb + 2 * p + c) * HW_;
                        float v0 = wa.x * __ldg(g + off[k][0][0]);
                        v0 = fmaf(wa.y, __ldg(g + off[k][0][1]), v0);
                        v0 = fmaf(wa.z, __ldg(g + off[k][0][2]), v0);
                        v0 = fmaf(wa.w, __ldg(g + off[k][0][3]), v0);
                        float v1 = wb.x * __ldg(g + off[k][1][0]);
                        v1 = fmaf(wb.y, __ldg(g + off[k][1][1]), v1);
                        v1 = fmaf(wb.z, __ldg(g + off[k][1][2]), v1);
                        v1 = fmaf(wb.w, __ldg(g + off[k][1][3]), v1);
                        float2* op = (float2*)(og + (size_t)(cb + 2 * p + c) * HOWO_) + obase[k];
                        *op = make_float2(v0, v1);
                    }
                }
            }
        }
    }
}

// ---------------------------------------------------------------------------
extern "C" void kernel_launch(void* const* d_in, const int* in_sizes, int n_in,
                              void* d_out, int out_size)
{
    const float* x     = (const float*)d_in[0];
    const float* w_off = (const float*)d_in[1];
    const float* b_off = (const float*)d_in[2];
    float* out = (float*)d_out;

    dysample_offset_kernel<<<B_ * HW_ / 256, 128>>>(x, w_off, b_off);
    dysample_sample_kernel<<<dim3(48, B_ * G_), dim3(192)>>>(x, out);
}